// round 11
// baseline (speedup 1.0000x reference)
#include <cuda_runtime.h>
#include <cuda_bf16.h>
#include <cuda_fp16.h>
#include <cstdint>
#include <math.h>

#define HID 128
#define MAXN 50000
#define MAXE 800000

typedef unsigned long long ull;

// ---------------- scratch (device globals; zero-initialized at load) ----------------
__device__ int   g_counts[MAXN + 1];   // scan_kernel re-zeroes after use each call
__device__ int   g_off[MAXN + 1];
__device__ int   g_cursor[MAXN];
__device__ int   g_esrc[MAXE];
__device__ float g_aggr[(size_t)MAXN * HID];
__device__ float g_h1[(size_t)MAXN * HID];
__device__ float g_h2[(size_t)MAXN * HID];
// W fp16, pre-laid-out as [col][264 halves] (word stride 132), per layer
__device__ uint4 g_whi[2][4224];   // 2 x 67584 B

#define MMA_F16(c, a0, a1, a2, a3, b0, b1) \
    asm volatile("mma.sync.aligned.m16n8k16.row.col.f32.f16.f16.f32 " \
        "{%0,%1,%2,%3}, {%4,%5,%6,%7}, {%8,%9}, {%0,%1,%2,%3};" \
        : "+f"((c)[0]), "+f"((c)[1]), "+f"((c)[2]), "+f"((c)[3]) \
        : "r"(a0), "r"(a1), "r"(a2), "r"(a3), "r"(b0), "r"(b1))

// ---------------- CSR build ----------------
__global__ void hist_kernel(const int* __restrict__ dst, int* __restrict__ counts, int E) {
    int e = blockIdx.x * blockDim.x + threadIdx.x;
    if (e < E) atomicAdd(&counts[dst[e]], 1);
}

__global__ void scan_kernel(int* __restrict__ counts, int* __restrict__ off,
                            int* __restrict__ cursor, int n) {
    __shared__ int part[1024];
    int tid = threadIdx.x;
    int chunk = (n + 1023) >> 10;
    int start = tid * chunk;
    int end = start + chunk; if (end > n) end = n;
    int s = 0;
    #pragma unroll 4
    for (int i = start; i < end; i++) s += counts[i];
    part[tid] = s;
    __syncthreads();
    for (int d = 1; d < 1024; d <<= 1) {
        int v = (tid >= d) ? part[tid - d] : 0;
        __syncthreads();
        part[tid] += v;
        __syncthreads();
    }
    int pre = (tid == 0) ? 0 : part[tid - 1];
    for (int i = start; i < end; i++) {
        int c = counts[i];
        counts[i] = 0;          // leave zeroed for next call's hist
        off[i] = pre;
        cursor[i] = pre;
        pre += c;
    }
    if (end == n) off[n] = pre;
}

__global__ void fill_kernel(const int* __restrict__ src, const int* __restrict__ dst,
                            int* __restrict__ cursor, int* __restrict__ esrc, int E) {
    int e = blockIdx.x * blockDim.x + threadIdx.x;
    if (e < E) {
        int d = dst[e];
        int pos = atomicAdd(&cursor[d], 1);
        esrc[pos] = src[e];
    }
}

// ---------------- W fp16 (once per call, both layers) ----------------
// layout: half index col*264 + k  (word stride 132; matches layer smem layout)
__global__ void wsplit_kernel(const float* __restrict__ W1l, const float* __restrict__ W1r,
                              const float* __restrict__ W2l, const float* __restrict__ W2r) {
    int idx = blockIdx.x * blockDim.x + threadIdx.x;   // 2*256*128 = 65536
    if (idx >= 2 * 256 * 128) return;
    int layer = idx >> 15;
    int r = idx & 32767;
    int k = r >> 7;
    int col = r & 127;
    const float* srcm;
    if (layer == 0) srcm = (k < 128) ? (W1l + (size_t)k * 128) : (W1r + (size_t)(k - 128) * 128);
    else            srcm = (k < 128) ? (W2l + (size_t)k * 128) : (W2r + (size_t)(k - 128) * 128);
    float w = srcm[col];
    __half h = __float2half(w);
    ((uint16_t*)g_whi[layer])[col * 264 + k] = *(uint16_t*)&h;
}

// ---------------- gather-aggregate (mean): warp per dst node, MLP=4 ----------------
__global__ void gather_kernel(const float* __restrict__ feat, const int* __restrict__ esrc,
                              const int* __restrict__ off, float* __restrict__ aggr, int n) {
    int w = (blockIdx.x * blockDim.x + threadIdx.x) >> 5;
    int lane = threadIdx.x & 31;
    if (w >= n) return;
    int o0 = off[w], o1 = off[w + 1];
    const float4* f4 = (const float4*)feat;
    float4 a0 = {0.f, 0.f, 0.f, 0.f};
    float4 a1 = {0.f, 0.f, 0.f, 0.f};
    int k = o0;
    for (; k + 4 <= o1; k += 4) {
        int s0 = __ldg(esrc + k);
        int s1 = __ldg(esrc + k + 1);
        int s2 = __ldg(esrc + k + 2);
        int s3 = __ldg(esrc + k + 3);
        float4 v0 = f4[(size_t)s0 * 32 + lane];
        float4 v1 = f4[(size_t)s1 * 32 + lane];
        float4 v2 = f4[(size_t)s2 * 32 + lane];
        float4 v3 = f4[(size_t)s3 * 32 + lane];
        a0.x += v0.x; a0.y += v0.y; a0.z += v0.z; a0.w += v0.w;
        a1.x += v1.x; a1.y += v1.y; a1.z += v1.z; a1.w += v1.w;
        a0.x += v2.x; a0.y += v2.y; a0.z += v2.z; a0.w += v2.w;
        a1.x += v3.x; a1.y += v3.y; a1.z += v3.z; a1.w += v3.w;
    }
    for (; k < o1; k++) {
        int s = __ldg(esrc + k);
        float4 v = f4[(size_t)s * 32 + lane];
        a0.x += v.x; a0.y += v.y; a0.z += v.z; a0.w += v.w;
    }
    float inv = 1.0f / fmaxf((float)(o1 - o0), 1.0f);
    float4 r;
    r.x = (a0.x + a1.x) * inv;
    r.y = (a0.y + a1.y) * inv;
    r.z = (a0.z + a1.z) * inv;
    r.w = (a0.w + a1.w) * inv;
    ((float4*)aggr)[(size_t)w * 32 + lane] = r;
}

// ---------------- HMMA (mma.sync fp16, 1-term) SAGE layer ----------------
// out[i][j] = relu( b[j] + sum_{k<256} S[i][k] W[k][j] ), S=[A|X], W=[Wl;Wr].
// W fp16 (precomputed); S fp16.  D = S*W, f32 accum.
// smem (word-indexed, k-pair-major):
//   sW[col][p], p=k/2 in 0..127, row stride 132 words (copied linearly from gmem)
//   sS[node][p], p in 0..63 per 128-k chunk, row stride 68 words
// Fragments (m16n8k16.row.col, g=lane>>2, t=lane&3, p0=kstep*8, W chunk base kc*64):
//   a0=sS[m0+g][p0+t] a1=sS[m0+g+8][p0+t] a2=sS[m0+g][p0+t+4] a3=sS[m0+g+8][p0+t+4]
//   b0=sW[n0+g][kc*64+p0+t] b1=sW[n0+g][kc*64+p0+t+4]
// Warp w owns cols [16w,16w+16) (2 n-tiles), loops 8 m-tiles; acc = 8*2*4 = 64 f32.
#define WSTRIDE 132
#define SSTRIDE 68
#define SM_BIAS 0
#define SM_WHI  512
#define SM_S    (512 + 128 * WSTRIDE * 4)
#define LAYER_SMEM (SM_S + 128 * SSTRIDE * 4)

__global__ void __launch_bounds__(256, 1)
layer_kernel(const float* __restrict__ A, const float* __restrict__ X,
             const uint4* __restrict__ whi,
             const float* __restrict__ bias, float* __restrict__ out, int n) {
    extern __shared__ char smem[];
    float* sBias = (float*)(smem + SM_BIAS);
    uint32_t* sWhi = (uint32_t*)(smem + SM_WHI);
    uint32_t* sS   = (uint32_t*)(smem + SM_S);

    int tid = threadIdx.x;
    int wid = tid >> 5;
    int lane = tid & 31;
    int g = lane >> 2;
    int t = lane & 3;
    int n0 = wid * 16;

    // ---- stage W: pure linear copy (4224 uint4) ----
    {
        uint4* dh = (uint4*)sWhi;
        for (int i = tid; i < 4224; i += 256) dh[i] = whi[i];
        if (tid < 128) sBias[tid] = bias[tid];
    }

    int nTiles = (n + 127) >> 7;
    for (int tile = blockIdx.x; tile < nTiles; tile += gridDim.x) {
        float acc[8][2][4];
        #pragma unroll
        for (int m = 0; m < 8; m++)
            #pragma unroll
            for (int nt = 0; nt < 2; nt++)
                #pragma unroll
                for (int q = 0; q < 4; q++) acc[m][nt][q] = 0.f;

        #pragma unroll
        for (int kc = 0; kc < 2; kc++) {
            __syncthreads();   // protects sS reuse (and sW staging on first pass)
            // stage S chunk (128 nodes x 128 k) as fp16: warp = 1 node row / pass
            {
                int q = tid & 31;          // float4 index 0..31 within row
                int nl0 = tid >> 5;        // 0..7
                const float* base = (kc == 0) ? A : X;
                #pragma unroll
                for (int pass = 0; pass < 16; pass++) {
                    int nodeLoc = pass * 8 + nl0;
                    int node = tile * 128 + nodeLoc;
                    float4 v;
                    if (node < n) v = *(const float4*)(base + (size_t)node * HID + q * 4);
                    else v = make_float4(0.f, 0.f, 0.f, 0.f);
                    __half2 h0 = __float22half2_rn(make_float2(v.x, v.y));
                    __half2 h1 = __float22half2_rn(make_float2(v.z, v.w));
                    uint32_t w0 = *(uint32_t*)&h0;
                    uint32_t w1 = *(uint32_t*)&h1;
                    int wi = nodeLoc * SSTRIDE + 2 * q;   // word index, 8B aligned
                    *(ull*)(sS + wi) = (ull)w0 | ((ull)w1 << 32);
                }
            }
            __syncthreads();

            #pragma unroll
            for (int kstep = 0; kstep < 8; kstep++) {
                int p0 = kstep * 8;
                // B fragments for 2 n-tiles  (+ kc*64 selects the K-chunk)
                uint32_t bf[2][2];
                #pragma unroll
                for (int nt = 0; nt < 2; nt++) {
                    int wrow = (n0 + nt * 8 + g) * WSTRIDE + kc * 64 + p0 + t;
                    bf[nt][0] = sWhi[wrow];
                    bf[nt][1] = sWhi[wrow + 4];
                }
                #pragma unroll
                for (int m = 0; m < 8; m++) {
                    int r0 = (m * 16 + g) * SSTRIDE + p0 + t;
                    int r1 = r0 + 8 * SSTRIDE;
                    uint32_t a0 = sS[r0], a1 = sS[r1];
                    uint32_t a2 = sS[r0 + 4], a3 = sS[r1 + 4];
                    #pragma unroll
                    for (int nt = 0; nt < 2; nt++) {
                        MMA_F16(acc[m][nt], a0, a1, a2, a3, bf[nt][0], bf[nt][1]);
                    }
                }
            }
        }

        // epilogue: bias + relu + store. Thread (m,nt): rows m*16+g, +8; cols n0+nt*8+2t,+1.
        #pragma unroll
        for (int m = 0; m < 8; m++) {
            #pragma unroll
            for (int nt = 0; nt < 2; nt++) {
                int col = n0 + nt * 8 + 2 * t;
                float b0 = sBias[col], b1 = sBias[col + 1];
                int node0 = tile * 128 + m * 16 + g;
                if (node0 < n) {
                    float2 o;
                    o.x = fmaxf(acc[m][nt][0] + b0, 0.f);
                    o.y = fmaxf(acc[m][nt][1] + b1, 0.f);
                    *(float2*)(out + (size_t)node0 * HID + col) = o;
                }
                int node1 = node0 + 8;
                if (node1 < n) {
                    float2 o;
                    o.x = fmaxf(acc[m][nt][2] + b0, 0.f);
                    o.y = fmaxf(acc[m][nt][3] + b1, 0.f);
                    *(float2*)(out + (size_t)node1 * HID + col) = o;
                }
            }
        }
    }
}

// ---------------- logits head: warp per node ----------------
__global__ void logits_kernel(const float* __restrict__ h, const float* __restrict__ Wout,
                              const float* __restrict__ bout, float* __restrict__ out, int n) {
    int w = (blockIdx.x * blockDim.x + threadIdx.x) >> 5;
    int lane = threadIdx.x & 31;
    if (w >= n) return;
    float4 v = ((const float4*)(h + (size_t)w * HID))[lane];
    int k = lane * 4;
    float s0 = v.x * Wout[(k + 0) * 2 + 0] + v.y * Wout[(k + 1) * 2 + 0] +
               v.z * Wout[(k + 2) * 2 + 0] + v.w * Wout[(k + 3) * 2 + 0];
    float s1 = v.x * Wout[(k + 0) * 2 + 1] + v.y * Wout[(k + 1) * 2 + 1] +
               v.z * Wout[(k + 2) * 2 + 1] + v.w * Wout[(k + 3) * 2 + 1];
    #pragma unroll
    for (int off = 16; off > 0; off >>= 1) {
        s0 += __shfl_xor_sync(0xFFFFFFFFu, s0, off);
        s1 += __shfl_xor_sync(0xFFFFFFFFu, s1, off);
    }
    if (lane == 0) {
        out[(size_t)w * 2 + 0] = s0 + bout[0];
        out[(size_t)w * 2 + 1] = s1 + bout[1];
    }
}

// ---------------- launch ----------------
extern "C" void kernel_launch(void* const* d_in, const int* in_sizes, int n_in,
                              void* d_out, int out_size) {
    const float* x    = (const float*)d_in[0];
    const int*   ei   = (const int*)d_in[1];   // int32 on device
    const float* W1l  = (const float*)d_in[2];
    const float* W1r  = (const float*)d_in[3];
    const float* b1   = (const float*)d_in[4];
    const float* W2l  = (const float*)d_in[5];
    const float* W2r  = (const float*)d_in[6];
    const float* b2   = (const float*)d_in[7];
    const float* Wout = (const float*)d_in[8];
    const float* bout = (const float*)d_in[9];
    float* dout = (float*)d_out;

    int n = in_sizes[0] / HID;
    int E = in_sizes[1] / 2;
    const int* src = ei;
    const int* dst = ei + E;

    int *p_counts, *p_off, *p_cursor, *p_esrc;
    float *p_aggr, *p_h1, *p_h2;
    uint4 *p_whi;
    cudaGetSymbolAddress((void**)&p_counts, g_counts);
    cudaGetSymbolAddress((void**)&p_off,    g_off);
    cudaGetSymbolAddress((void**)&p_cursor, g_cursor);
    cudaGetSymbolAddress((void**)&p_esrc,   g_esrc);
    cudaGetSymbolAddress((void**)&p_aggr,   g_aggr);
    cudaGetSymbolAddress((void**)&p_h1,     g_h1);
    cudaGetSymbolAddress((void**)&p_h2,     g_h2);
    cudaGetSymbolAddress((void**)&p_whi,    g_whi);

    cudaFuncSetAttribute(layer_kernel, cudaFuncAttributeMaxDynamicSharedMemorySize, LAYER_SMEM);

    // tuple output: logits [n*2] then h [n*128]
    float* hOut = ((size_t)out_size >= (size_t)n * (HID + 2)) ? (dout + (size_t)n * 2) : p_h2;

    // ---- launches 1-4: CSR build + W convert (layer1 is launch #6) ----
    hist_kernel<<<(E + 255) / 256, 256>>>(dst, p_counts, E);
    scan_kernel<<<1, 1024>>>(p_counts, p_off, p_cursor, n);
    fill_kernel<<<(E + 255) / 256, 256>>>(src, dst, p_cursor, p_esrc, E);
    wsplit_kernel<<<256, 256>>>(W1l, W1r, W2l, W2r);

    int gatherGrid = (n * 32 + 255) / 256;
    int nTiles = (n + 127) >> 7;
    int layerGrid = nTiles < 148 ? nTiles : 148;

    // ---- layer 1 ----
    gather_kernel<<<gatherGrid, 256>>>(x, p_esrc, p_off, p_aggr, n);
    layer_kernel<<<layerGrid, 256, LAYER_SMEM>>>(p_aggr, x, p_whi, b1, p_h1, n);

    // ---- layer 2 ----
    gather_kernel<<<gatherGrid, 256>>>(p_h1, p_esrc, p_off, p_aggr, n);
    layer_kernel<<<layerGrid, 256, LAYER_SMEM>>>(p_aggr, p_h1, p_whi + 4224, b2, hOut, n);

    // ---- head ----
    logits_kernel<<<(n * 32 + 255) / 256, 256>>>(hOut, Wout, bout, dout, n);
}

// round 12
// speedup vs baseline: 1.5325x; 1.5325x over previous
#include <cuda_runtime.h>
#include <cuda_bf16.h>
#include <cuda_fp16.h>
#include <cstdint>
#include <math.h>

#define HID 128
#define MAXN 50000
#define MAXE 800000

typedef unsigned long long ull;

// ---------------- scratch (device globals; zero-initialized at load) ----------------
__device__ int   g_counts[MAXN + 1];   // scan_kernel re-zeroes after use each call
__device__ int   g_off[MAXN + 1];
__device__ int   g_cursor[MAXN];
__device__ int   g_esrc[MAXE];
__device__ ull   g_x16[(size_t)MAXN * 32];    // x as fp16 rows (128 halves = 32 ull)
__device__ ull   g_h16[(size_t)MAXN * 32];    // h1 as fp16 rows
__device__ ull   g_aggr16[(size_t)MAXN * 32]; // mean-aggregated features, fp16
__device__ float g_h2[(size_t)MAXN * HID];    // fallback h buffer (fp32)
// W fp16, pre-laid-out as [col][264 halves] (word stride 132), per layer
__device__ uint4 g_whi[2][4224];   // 2 x 67584 B

#define MMA_F16(c, a0, a1, a2, a3, b0, b1) \
    asm volatile("mma.sync.aligned.m16n8k16.row.col.f32.f16.f16.f32 " \
        "{%0,%1,%2,%3}, {%4,%5,%6,%7}, {%8,%9}, {%0,%1,%2,%3};" \
        : "+f"((c)[0]), "+f"((c)[1]), "+f"((c)[2]), "+f"((c)[3]) \
        : "r"(a0), "r"(a1), "r"(a2), "r"(a3), "r"(b0), "r"(b1))

// ---------------- CSR build ----------------
__global__ void hist_kernel(const int* __restrict__ dst, int* __restrict__ counts, int E) {
    int e = blockIdx.x * blockDim.x + threadIdx.x;
    if (e < E) atomicAdd(&counts[dst[e]], 1);
}

__global__ void scan_kernel(int* __restrict__ counts, int* __restrict__ off,
                            int* __restrict__ cursor, int n) {
    __shared__ int part[1024];
    int tid = threadIdx.x;
    int chunk = (n + 1023) >> 10;
    int start = tid * chunk;
    int end = start + chunk; if (end > n) end = n;
    int s = 0;
    #pragma unroll 4
    for (int i = start; i < end; i++) s += counts[i];
    part[tid] = s;
    __syncthreads();
    for (int d = 1; d < 1024; d <<= 1) {
        int v = (tid >= d) ? part[tid - d] : 0;
        __syncthreads();
        part[tid] += v;
        __syncthreads();
    }
    int pre = (tid == 0) ? 0 : part[tid - 1];
    for (int i = start; i < end; i++) {
        int c = counts[i];
        counts[i] = 0;          // leave zeroed for next call's hist
        off[i] = pre;
        cursor[i] = pre;
        pre += c;
    }
    if (end == n) off[n] = pre;
}

__global__ void fill_kernel(const int* __restrict__ src, const int* __restrict__ dst,
                            int* __restrict__ cursor, int* __restrict__ esrc, int E) {
    int e = blockIdx.x * blockDim.x + threadIdx.x;
    if (e < E) {
        int d = dst[e];
        int pos = atomicAdd(&cursor[d], 1);
        esrc[pos] = src[e];
    }
}

// ---------------- W fp16 (once per call, both layers) ----------------
__global__ void wsplit_kernel(const float* __restrict__ W1l, const float* __restrict__ W1r,
                              const float* __restrict__ W2l, const float* __restrict__ W2r) {
    int idx = blockIdx.x * blockDim.x + threadIdx.x;   // 2*256*128 = 65536
    if (idx >= 2 * 256 * 128) return;
    int layer = idx >> 15;
    int r = idx & 32767;
    int k = r >> 7;
    int col = r & 127;
    const float* srcm;
    if (layer == 0) srcm = (k < 128) ? (W1l + (size_t)k * 128) : (W1r + (size_t)(k - 128) * 128);
    else            srcm = (k < 128) ? (W2l + (size_t)k * 128) : (W2r + (size_t)(k - 128) * 128);
    float w = srcm[col];
    __half h = __float2half(w);
    ((uint16_t*)g_whi[layer])[col * 264 + k] = *(uint16_t*)&h;
}

// ---------------- x -> fp16 convert (once per call) ----------------
__global__ void xcvt_kernel(const float* __restrict__ x, ull* __restrict__ x16, int total4) {
    int i = blockIdx.x * blockDim.x + threadIdx.x;   // one per 4 floats
    if (i >= total4) return;
    float4 v = ((const float4*)x)[i];
    __half2 h0 = __float22half2_rn(make_float2(v.x, v.y));
    __half2 h1 = __float22half2_rn(make_float2(v.z, v.w));
    x16[i] = (ull)(*(uint32_t*)&h0) | ((ull)(*(uint32_t*)&h1) << 32);
}

// ---------------- gather-aggregate (mean) over fp16 rows: warp per dst node ----------------
__global__ void gather_kernel(const ull* __restrict__ feat16, const int* __restrict__ esrc,
                              const int* __restrict__ off, ull* __restrict__ aggr16, int n) {
    int w = (blockIdx.x * blockDim.x + threadIdx.x) >> 5;
    int lane = threadIdx.x & 31;
    if (w >= n) return;
    int o0 = off[w], o1 = off[w + 1];
    float a0 = 0.f, a1 = 0.f, a2 = 0.f, a3 = 0.f;
    int k = o0;
    for (; k + 4 <= o1; k += 4) {
        int s0 = __ldg(esrc + k);
        int s1 = __ldg(esrc + k + 1);
        int s2 = __ldg(esrc + k + 2);
        int s3 = __ldg(esrc + k + 3);
        ull v0 = feat16[(size_t)s0 * 32 + lane];
        ull v1 = feat16[(size_t)s1 * 32 + lane];
        ull v2 = feat16[(size_t)s2 * 32 + lane];
        ull v3 = feat16[(size_t)s3 * 32 + lane];
        #pragma unroll
        for (int e = 0; e < 4; e++) {
            ull v = (e == 0) ? v0 : (e == 1) ? v1 : (e == 2) ? v2 : v3;
            uint32_t lo = (uint32_t)v, hi = (uint32_t)(v >> 32);
            float2 f0 = __half22float2(*(__half2*)&lo);
            float2 f1 = __half22float2(*(__half2*)&hi);
            a0 += f0.x; a1 += f0.y; a2 += f1.x; a3 += f1.y;
        }
    }
    for (; k < o1; k++) {
        int s = __ldg(esrc + k);
        ull v = feat16[(size_t)s * 32 + lane];
        uint32_t lo = (uint32_t)v, hi = (uint32_t)(v >> 32);
        float2 f0 = __half22float2(*(__half2*)&lo);
        float2 f1 = __half22float2(*(__half2*)&hi);
        a0 += f0.x; a1 += f0.y; a2 += f1.x; a3 += f1.y;
    }
    float inv = 1.0f / fmaxf((float)(o1 - o0), 1.0f);
    __half2 r0 = __float22half2_rn(make_float2(a0 * inv, a1 * inv));
    __half2 r1 = __float22half2_rn(make_float2(a2 * inv, a3 * inv));
    aggr16[(size_t)w * 32 + lane] = (ull)(*(uint32_t*)&r0) | ((ull)(*(uint32_t*)&r1) << 32);
}

// ---------------- HMMA (mma.sync fp16, 1-term) SAGE layer, fp16 inputs ----------------
// out[i][j] = relu( b[j] + sum_{k<256} S[i][k] W[k][j] ), S=[A|X] (fp16), W=[Wl;Wr] (fp16).
// smem layouts as before: sW[col][p] stride 132 words; sS[node][p] stride 68 words.
// Writes h as fp16 (layer 1) or fp32 (layer 2) per outIsF16.
#define WSTRIDE 132
#define SSTRIDE 68
#define SM_BIAS 0
#define SM_WHI  512
#define SM_S    (512 + 128 * WSTRIDE * 4)
#define LAYER_SMEM (SM_S + 128 * SSTRIDE * 4)

__global__ void __launch_bounds__(256, 1)
layer_kernel(const ull* __restrict__ A16, const ull* __restrict__ X16,
             const uint4* __restrict__ whi, const float* __restrict__ bias,
             float* __restrict__ outF32, ull* __restrict__ outF16,
             int n, int outIsF16) {
    extern __shared__ char smem[];
    float* sBias = (float*)(smem + SM_BIAS);
    uint32_t* sWhi = (uint32_t*)(smem + SM_WHI);
    uint32_t* sS   = (uint32_t*)(smem + SM_S);

    int tid = threadIdx.x;
    int wid = tid >> 5;
    int lane = tid & 31;
    int g = lane >> 2;
    int t = lane & 3;
    int n0 = wid * 16;

    // ---- stage W: pure linear copy (4224 uint4) ----
    {
        uint4* dh = (uint4*)sWhi;
        for (int i = tid; i < 4224; i += 256) dh[i] = whi[i];
        if (tid < 128) sBias[tid] = bias[tid];
    }

    int nTiles = (n + 127) >> 7;
    for (int tile = blockIdx.x; tile < nTiles; tile += gridDim.x) {
        float acc[8][2][4];
        #pragma unroll
        for (int m = 0; m < 8; m++)
            #pragma unroll
            for (int nt = 0; nt < 2; nt++)
                #pragma unroll
                for (int q = 0; q < 4; q++) acc[m][nt][q] = 0.f;

        #pragma unroll
        for (int kc = 0; kc < 2; kc++) {
            __syncthreads();   // protects sS reuse (and sW staging on first pass)
            // stage S chunk (128 nodes x 128 k): pure 8B copy, warp = 1 node row / pass
            {
                int q = tid & 31;          // ull index 0..31 within row
                int nl0 = tid >> 5;        // 0..7
                const ull* base = (kc == 0) ? A16 : X16;
                #pragma unroll
                for (int pass = 0; pass < 16; pass++) {
                    int nodeLoc = pass * 8 + nl0;
                    int node = tile * 128 + nodeLoc;
                    ull v = (node < n) ? base[(size_t)node * 32 + q] : 0ull;
                    *(ull*)(sS + nodeLoc * SSTRIDE + 2 * q) = v;
                }
            }
            __syncthreads();

            #pragma unroll
            for (int kstep = 0; kstep < 8; kstep++) {
                int p0 = kstep * 8;
                uint32_t bf[2][2];
                #pragma unroll
                for (int nt = 0; nt < 2; nt++) {
                    int wrow = (n0 + nt * 8 + g) * WSTRIDE + kc * 64 + p0 + t;
                    bf[nt][0] = sWhi[wrow];
                    bf[nt][1] = sWhi[wrow + 4];
                }
                #pragma unroll
                for (int m = 0; m < 8; m++) {
                    int r0 = (m * 16 + g) * SSTRIDE + p0 + t;
                    int r1 = r0 + 8 * SSTRIDE;
                    uint32_t a0 = sS[r0], a1 = sS[r1];
                    uint32_t a2 = sS[r0 + 4], a3 = sS[r1 + 4];
                    #pragma unroll
                    for (int nt = 0; nt < 2; nt++) {
                        MMA_F16(acc[m][nt], a0, a1, a2, a3, bf[nt][0], bf[nt][1]);
                    }
                }
            }
        }

        // epilogue: bias + relu; store fp16 (layer1) or fp32 (layer2).
        #pragma unroll
        for (int m = 0; m < 8; m++) {
            #pragma unroll
            for (int nt = 0; nt < 2; nt++) {
                int col = n0 + nt * 8 + 2 * t;
                float b0 = sBias[col], b1 = sBias[col + 1];
                int node0 = tile * 128 + m * 16 + g;
                int node1 = node0 + 8;
                float v00 = fmaxf(acc[m][nt][0] + b0, 0.f);
                float v01 = fmaxf(acc[m][nt][1] + b1, 0.f);
                float v10 = fmaxf(acc[m][nt][2] + b0, 0.f);
                float v11 = fmaxf(acc[m][nt][3] + b1, 0.f);
                if (outIsF16) {
                    __half* o16 = (__half*)outF16;
                    if (node0 < n) {
                        __half2 h = __float22half2_rn(make_float2(v00, v01));
                        *(__half2*)(o16 + (size_t)node0 * HID + col) = h;
                    }
                    if (node1 < n) {
                        __half2 h = __float22half2_rn(make_float2(v10, v11));
                        *(__half2*)(o16 + (size_t)node1 * HID + col) = h;
                    }
                } else {
                    if (node0 < n) {
                        float2 o; o.x = v00; o.y = v01;
                        *(float2*)(outF32 + (size_t)node0 * HID + col) = o;
                    }
                    if (node1 < n) {
                        float2 o; o.x = v10; o.y = v11;
                        *(float2*)(outF32 + (size_t)node1 * HID + col) = o;
                    }
                }
            }
        }
    }
}

// ---------------- logits head: warp per node ----------------
__global__ void logits_kernel(const float* __restrict__ h, const float* __restrict__ Wout,
                              const float* __restrict__ bout, float* __restrict__ out, int n) {
    int w = (blockIdx.x * blockDim.x + threadIdx.x) >> 5;
    int lane = threadIdx.x & 31;
    if (w >= n) return;
    float4 v = ((const float4*)(h + (size_t)w * HID))[lane];
    int k = lane * 4;
    float s0 = v.x * Wout[(k + 0) * 2 + 0] + v.y * Wout[(k + 1) * 2 + 0] +
               v.z * Wout[(k + 2) * 2 + 0] + v.w * Wout[(k + 3) * 2 + 0];
    float s1 = v.x * Wout[(k + 0) * 2 + 1] + v.y * Wout[(k + 1) * 2 + 1] +
               v.z * Wout[(k + 2) * 2 + 1] + v.w * Wout[(k + 3) * 2 + 1];
    #pragma unroll
    for (int off = 16; off > 0; off >>= 1) {
        s0 += __shfl_xor_sync(0xFFFFFFFFu, s0, off);
        s1 += __shfl_xor_sync(0xFFFFFFFFu, s1, off);
    }
    if (lane == 0) {
        out[(size_t)w * 2 + 0] = s0 + bout[0];
        out[(size_t)w * 2 + 1] = s1 + bout[1];
    }
}

// ---------------- launch ----------------
extern "C" void kernel_launch(void* const* d_in, const int* in_sizes, int n_in,
                              void* d_out, int out_size) {
    const float* x    = (const float*)d_in[0];
    const int*   ei   = (const int*)d_in[1];   // int32 on device
    const float* W1l  = (const float*)d_in[2];
    const float* W1r  = (const float*)d_in[3];
    const float* b1   = (const float*)d_in[4];
    const float* W2l  = (const float*)d_in[5];
    const float* W2r  = (const float*)d_in[6];
    const float* b2   = (const float*)d_in[7];
    const float* Wout = (const float*)d_in[8];
    const float* bout = (const float*)d_in[9];
    float* dout = (float*)d_out;

    int n = in_sizes[0] / HID;
    int E = in_sizes[1] / 2;
    const int* src = ei;
    const int* dst = ei + E;

    int *p_counts, *p_off, *p_cursor, *p_esrc;
    ull *p_x16, *p_h16, *p_aggr16;
    float *p_h2;
    uint4 *p_whi;
    cudaGetSymbolAddress((void**)&p_counts, g_counts);
    cudaGetSymbolAddress((void**)&p_off,    g_off);
    cudaGetSymbolAddress((void**)&p_cursor, g_cursor);
    cudaGetSymbolAddress((void**)&p_esrc,   g_esrc);
    cudaGetSymbolAddress((void**)&p_x16,    g_x16);
    cudaGetSymbolAddress((void**)&p_h16,    g_h16);
    cudaGetSymbolAddress((void**)&p_aggr16, g_aggr16);
    cudaGetSymbolAddress((void**)&p_h2,     g_h2);
    cudaGetSymbolAddress((void**)&p_whi,    g_whi);

    cudaFuncSetAttribute(layer_kernel, cudaFuncAttributeMaxDynamicSharedMemorySize, LAYER_SMEM);

    // tuple output: logits [n*2] then h [n*128]
    float* hOut = ((size_t)out_size >= (size_t)n * (HID + 2)) ? (dout + (size_t)n * 2) : p_h2;

    // ---- launches 1-5: CSR build + W convert + x convert (gather1 is launch #6) ----
    hist_kernel<<<(E + 255) / 256, 256>>>(dst, p_counts, E);
    scan_kernel<<<1, 1024>>>(p_counts, p_off, p_cursor, n);
    fill_kernel<<<(E + 255) / 256, 256>>>(src, dst, p_cursor, p_esrc, E);
    wsplit_kernel<<<256, 256>>>(W1l, W1r, W2l, W2r);
    int total4 = n * HID / 4;
    xcvt_kernel<<<(total4 + 255) / 256, 256>>>(x, p_x16, total4);

    int gatherGrid = (n * 32 + 255) / 256;
    int nTiles = (n + 127) >> 7;
    int layerGrid = nTiles < 148 ? nTiles : 148;

    // ---- layer 1 (h1 stored fp16) ----
    gather_kernel<<<gatherGrid, 256>>>(p_x16, p_esrc, p_off, p_aggr16, n);
    layer_kernel<<<layerGrid, 256, LAYER_SMEM>>>(p_aggr16, p_x16, p_whi, b1,
                                                 nullptr, p_h16, n, 1);

    // ---- layer 2 (h stored fp32 to output) ----
    gather_kernel<<<gatherGrid, 256>>>(p_h16, p_esrc, p_off, p_aggr16, n);
    layer_kernel<<<layerGrid, 256, LAYER_SMEM>>>(p_aggr16, p_h16, p_whi + 4224, b2,
                                                 hOut, nullptr, n, 0);

    // ---- head ----
    logits_kernel<<<(n * 32 + 255) / 256, 256>>>(hOut, Wout, bout, dout, n);
}

// round 13
// speedup vs baseline: 1.5484x; 1.0104x over previous
#include <cuda_runtime.h>
#include <cuda_bf16.h>
#include <cuda_fp16.h>
#include <cstdint>
#include <math.h>

#define HID 128
#define MAXN 50000
#define MAXE 800000

typedef unsigned long long ull;

// ---------------- scratch (device globals; zero-initialized at load) ----------------
__device__ int   g_counts[MAXN + 1];   // scan_kernel re-zeroes after use each call
__device__ int   g_off[MAXN + 1];
__device__ int   g_cursor[MAXN];
__device__ int   g_esrc[MAXE];
__device__ ull   g_x16[(size_t)MAXN * 32];    // x as fp16 rows (128 halves = 32 ull)
__device__ ull   g_h16[(size_t)MAXN * 32];    // h1 as fp16 rows
__device__ ull   g_aggr16[(size_t)MAXN * 32]; // mean-aggregated features, fp16
__device__ float g_h2[(size_t)MAXN * HID];    // fallback h buffer (fp32)
// W fp16, pre-laid-out as [col][264 halves] (word stride 132), per layer
__device__ uint4 g_whi[2][4224];   // 2 x 67584 B

#define MMA_F16(c, a0, a1, a2, a3, b0, b1) \
    asm volatile("mma.sync.aligned.m16n8k16.row.col.f32.f16.f16.f32 " \
        "{%0,%1,%2,%3}, {%4,%5,%6,%7}, {%8,%9}, {%0,%1,%2,%3};" \
        : "+f"((c)[0]), "+f"((c)[1]), "+f"((c)[2]), "+f"((c)[3]) \
        : "r"(a0), "r"(a1), "r"(a2), "r"(a3), "r"(b0), "r"(b1))

// ---------------- CSR build ----------------
__global__ void hist_kernel(const int* __restrict__ dst, int* __restrict__ counts, int E) {
    int e = blockIdx.x * blockDim.x + threadIdx.x;
    if (e < E) atomicAdd(&counts[dst[e]], 1);
}

__global__ void scan_kernel(int* __restrict__ counts, int* __restrict__ off,
                            int* __restrict__ cursor, int n) {
    __shared__ int part[1024];
    int tid = threadIdx.x;
    int chunk = (n + 1023) >> 10;
    int start = tid * chunk;
    int end = start + chunk; if (end > n) end = n;
    int s = 0;
    #pragma unroll 4
    for (int i = start; i < end; i++) s += counts[i];
    part[tid] = s;
    __syncthreads();
    for (int d = 1; d < 1024; d <<= 1) {
        int v = (tid >= d) ? part[tid - d] : 0;
        __syncthreads();
        part[tid] += v;
        __syncthreads();
    }
    int pre = (tid == 0) ? 0 : part[tid - 1];
    for (int i = start; i < end; i++) {
        int c = counts[i];
        counts[i] = 0;          // leave zeroed for next call's hist
        off[i] = pre;
        cursor[i] = pre;
        pre += c;
    }
    if (end == n) off[n] = pre;
}

__global__ void fill_kernel(const int* __restrict__ src, const int* __restrict__ dst,
                            int* __restrict__ cursor, int* __restrict__ esrc, int E) {
    int e = blockIdx.x * blockDim.x + threadIdx.x;
    if (e < E) {
        int d = dst[e];
        int pos = atomicAdd(&cursor[d], 1);
        esrc[pos] = src[e];
    }
}

// ---------------- W fp16 (once per call, both layers) ----------------
__global__ void wsplit_kernel(const float* __restrict__ W1l, const float* __restrict__ W1r,
                              const float* __restrict__ W2l, const float* __restrict__ W2r) {
    int idx = blockIdx.x * blockDim.x + threadIdx.x;   // 2*256*128 = 65536
    if (idx >= 2 * 256 * 128) return;
    int layer = idx >> 15;
    int r = idx & 32767;
    int k = r >> 7;
    int col = r & 127;
    const float* srcm;
    if (layer == 0) srcm = (k < 128) ? (W1l + (size_t)k * 128) : (W1r + (size_t)(k - 128) * 128);
    else            srcm = (k < 128) ? (W2l + (size_t)k * 128) : (W2r + (size_t)(k - 128) * 128);
    float w = srcm[col];
    __half h = __float2half(w);
    ((uint16_t*)g_whi[layer])[col * 264 + k] = *(uint16_t*)&h;
}

// ---------------- x -> fp16 convert (once per call) ----------------
__global__ void xcvt_kernel(const float* __restrict__ x, ull* __restrict__ x16, int total4) {
    int i = blockIdx.x * blockDim.x + threadIdx.x;   // one per 4 floats
    if (i >= total4) return;
    float4 v = ((const float4*)x)[i];
    __half2 h0 = __float22half2_rn(make_float2(v.x, v.y));
    __half2 h1 = __float22half2_rn(make_float2(v.z, v.w));
    x16[i] = (ull)(*(uint32_t*)&h0) | ((ull)(*(uint32_t*)&h1) << 32);
}

// ---------------- gather-aggregate (mean) over fp16 rows: warp per dst node ----------------
__global__ void gather_kernel(const ull* __restrict__ feat16, const int* __restrict__ esrc,
                              const int* __restrict__ off, ull* __restrict__ aggr16, int n) {
    int w = (blockIdx.x * blockDim.x + threadIdx.x) >> 5;
    int lane = threadIdx.x & 31;
    if (w >= n) return;
    int o0 = off[w], o1 = off[w + 1];
    float a0 = 0.f, a1 = 0.f, a2 = 0.f, a3 = 0.f;
    int k = o0;
    for (; k + 4 <= o1; k += 4) {
        int s0 = __ldg(esrc + k);
        int s1 = __ldg(esrc + k + 1);
        int s2 = __ldg(esrc + k + 2);
        int s3 = __ldg(esrc + k + 3);
        ull v0 = feat16[(size_t)s0 * 32 + lane];
        ull v1 = feat16[(size_t)s1 * 32 + lane];
        ull v2 = feat16[(size_t)s2 * 32 + lane];
        ull v3 = feat16[(size_t)s3 * 32 + lane];
        #pragma unroll
        for (int e = 0; e < 4; e++) {
            ull v = (e == 0) ? v0 : (e == 1) ? v1 : (e == 2) ? v2 : v3;
            uint32_t lo = (uint32_t)v, hi = (uint32_t)(v >> 32);
            float2 f0 = __half22float2(*(__half2*)&lo);
            float2 f1 = __half22float2(*(__half2*)&hi);
            a0 += f0.x; a1 += f0.y; a2 += f1.x; a3 += f1.y;
        }
    }
    for (; k < o1; k++) {
        int s = __ldg(esrc + k);
        ull v = feat16[(size_t)s * 32 + lane];
        uint32_t lo = (uint32_t)v, hi = (uint32_t)(v >> 32);
        float2 f0 = __half22float2(*(__half2*)&lo);
        float2 f1 = __half22float2(*(__half2*)&hi);
        a0 += f0.x; a1 += f0.y; a2 += f1.x; a3 += f1.y;
    }
    float inv = 1.0f / fmaxf((float)(o1 - o0), 1.0f);
    __half2 r0 = __float22half2_rn(make_float2(a0 * inv, a1 * inv));
    __half2 r1 = __float22half2_rn(make_float2(a2 * inv, a3 * inv));
    aggr16[(size_t)w * 32 + lane] = (ull)(*(uint32_t*)&r0) | ((ull)(*(uint32_t*)&r1) << 32);
}

// ---------------- HMMA (mma.sync fp16) SAGE layer, double-buffered S staging ----------------
// out[i][j] = relu( b[j] + sum_{k<256} S[i][k] W[k][j] ), S=[A|X] (fp16), W=[Wl;Wr] (fp16).
// smem: sW[col][p] stride 132 words; two sS buffers [node][p] stride 68 words.
// Pipeline per tile: stage(X)||MMA(A); sync; stage(nextA)||MMA(X); sync; epilogue.
#define WSTRIDE 132
#define SSTRIDE 68
#define SM_BIAS 0
#define SM_WHI  512
#define SM_S0   (512 + 128 * WSTRIDE * 4)
#define SM_S1   (SM_S0 + 128 * SSTRIDE * 4)
#define LAYER_SMEM (SM_S1 + 128 * SSTRIDE * 4)

__device__ __forceinline__ void stage_chunk(uint32_t* sS, const ull* __restrict__ base,
                                            int tile, int n, int tid) {
    int q = tid & 31;          // ull index 0..31 within row
    int nl0 = tid >> 5;        // 0..7
    #pragma unroll
    for (int pass = 0; pass < 16; pass++) {
        int nodeLoc = pass * 8 + nl0;
        int node = tile * 128 + nodeLoc;
        ull v = (node < n) ? base[(size_t)node * 32 + q] : 0ull;
        *(ull*)(sS + nodeLoc * SSTRIDE + 2 * q) = v;
    }
}

__device__ __forceinline__ void mma_chunk(float acc[8][2][4], const uint32_t* sS,
                                          const uint32_t* sWhi, int kc,
                                          int n0, int g, int t) {
    #pragma unroll
    for (int kstep = 0; kstep < 8; kstep++) {
        int p0 = kstep * 8;
        uint32_t bf[2][2];
        #pragma unroll
        for (int nt = 0; nt < 2; nt++) {
            int wrow = (n0 + nt * 8 + g) * WSTRIDE + kc * 64 + p0 + t;
            bf[nt][0] = sWhi[wrow];
            bf[nt][1] = sWhi[wrow + 4];
        }
        #pragma unroll
        for (int m = 0; m < 8; m++) {
            int r0 = (m * 16 + g) * SSTRIDE + p0 + t;
            int r1 = r0 + 8 * SSTRIDE;
            uint32_t a0 = sS[r0], a1 = sS[r1];
            uint32_t a2 = sS[r0 + 4], a3 = sS[r1 + 4];
            #pragma unroll
            for (int nt = 0; nt < 2; nt++) {
                MMA_F16(acc[m][nt], a0, a1, a2, a3, bf[nt][0], bf[nt][1]);
            }
        }
    }
}

__global__ void __launch_bounds__(256, 1)
layer_kernel(const ull* __restrict__ A16, const ull* __restrict__ X16,
             const uint4* __restrict__ whi, const float* __restrict__ bias,
             float* __restrict__ outF32, ull* __restrict__ outF16,
             int n, int outIsF16) {
    extern __shared__ char smem[];
    float* sBias = (float*)(smem + SM_BIAS);
    uint32_t* sWhi = (uint32_t*)(smem + SM_WHI);
    uint32_t* sS[2] = { (uint32_t*)(smem + SM_S0), (uint32_t*)(smem + SM_S1) };

    int tid = threadIdx.x;
    int wid = tid >> 5;
    int lane = tid & 31;
    int g = lane >> 2;
    int t = lane & 3;
    int n0 = wid * 16;

    // ---- stage W: pure linear copy (4224 uint4) ----
    {
        uint4* dh = (uint4*)sWhi;
        for (int i = tid; i < 4224; i += 256) dh[i] = whi[i];
        if (tid < 128) sBias[tid] = bias[tid];
    }

    int nTiles = (n + 127) >> 7;
    int firstTile = blockIdx.x;
    if (firstTile < nTiles) stage_chunk(sS[0], A16, firstTile, n, tid);
    __syncthreads();

    int cur = 0;
    for (int tile = firstTile; tile < nTiles; tile += gridDim.x) {
        float acc[8][2][4];
        #pragma unroll
        for (int m = 0; m < 8; m++)
            #pragma unroll
            for (int nt = 0; nt < 2; nt++)
                #pragma unroll
                for (int q = 0; q < 4; q++) acc[m][nt][q] = 0.f;

        // stage X-chunk into other buffer, MMA A-chunk from current
        stage_chunk(sS[cur ^ 1], X16, tile, n, tid);
        mma_chunk(acc, sS[cur], sWhi, 0, n0, g, t);
        __syncthreads();
        cur ^= 1;

        // stage next tile's A-chunk, MMA X-chunk
        int nextTile = tile + gridDim.x;
        if (nextTile < nTiles) stage_chunk(sS[cur ^ 1], A16, nextTile, n, tid);
        mma_chunk(acc, sS[cur], sWhi, 1, n0, g, t);
        __syncthreads();
        cur ^= 1;

        // epilogue: bias + relu; store fp16 (layer1) or fp32 (layer2).
        #pragma unroll
        for (int m = 0; m < 8; m++) {
            #pragma unroll
            for (int nt = 0; nt < 2; nt++) {
                int col = n0 + nt * 8 + 2 * t;
                float b0 = sBias[col], b1 = sBias[col + 1];
                int node0 = tile * 128 + m * 16 + g;
                int node1 = node0 + 8;
                float v00 = fmaxf(acc[m][nt][0] + b0, 0.f);
                float v01 = fmaxf(acc[m][nt][1] + b1, 0.f);
                float v10 = fmaxf(acc[m][nt][2] + b0, 0.f);
                float v11 = fmaxf(acc[m][nt][3] + b1, 0.f);
                if (outIsF16) {
                    __half* o16 = (__half*)outF16;
                    if (node0 < n) {
                        __half2 h = __float22half2_rn(make_float2(v00, v01));
                        *(__half2*)(o16 + (size_t)node0 * HID + col) = h;
                    }
                    if (node1 < n) {
                        __half2 h = __float22half2_rn(make_float2(v10, v11));
                        *(__half2*)(o16 + (size_t)node1 * HID + col) = h;
                    }
                } else {
                    if (node0 < n) {
                        float2 o; o.x = v00; o.y = v01;
                        *(float2*)(outF32 + (size_t)node0 * HID + col) = o;
                    }
                    if (node1 < n) {
                        float2 o; o.x = v10; o.y = v11;
                        *(float2*)(outF32 + (size_t)node1 * HID + col) = o;
                    }
                }
            }
        }
    }
}

// ---------------- logits head: warp per node ----------------
__global__ void logits_kernel(const float* __restrict__ h, const float* __restrict__ Wout,
                              const float* __restrict__ bout, float* __restrict__ out, int n) {
    int w = (blockIdx.x * blockDim.x + threadIdx.x) >> 5;
    int lane = threadIdx.x & 31;
    if (w >= n) return;
    float4 v = ((const float4*)(h + (size_t)w * HID))[lane];
    int k = lane * 4;
    float s0 = v.x * Wout[(k + 0) * 2 + 0] + v.y * Wout[(k + 1) * 2 + 0] +
               v.z * Wout[(k + 2) * 2 + 0] + v.w * Wout[(k + 3) * 2 + 0];
    float s1 = v.x * Wout[(k + 0) * 2 + 1] + v.y * Wout[(k + 1) * 2 + 1] +
               v.z * Wout[(k + 2) * 2 + 1] + v.w * Wout[(k + 3) * 2 + 1];
    #pragma unroll
    for (int off = 16; off > 0; off >>= 1) {
        s0 += __shfl_xor_sync(0xFFFFFFFFu, s0, off);
        s1 += __shfl_xor_sync(0xFFFFFFFFu, s1, off);
    }
    if (lane == 0) {
        out[(size_t)w * 2 + 0] = s0 + bout[0];
        out[(size_t)w * 2 + 1] = s1 + bout[1];
    }
}

// ---------------- launch ----------------
extern "C" void kernel_launch(void* const* d_in, const int* in_sizes, int n_in,
                              void* d_out, int out_size) {
    const float* x    = (const float*)d_in[0];
    const int*   ei   = (const int*)d_in[1];   // int32 on device
    const float* W1l  = (const float*)d_in[2];
    const float* W1r  = (const float*)d_in[3];
    const float* b1   = (const float*)d_in[4];
    const float* W2l  = (const float*)d_in[5];
    const float* W2r  = (const float*)d_in[6];
    const float* b2   = (const float*)d_in[7];
    const float* Wout = (const float*)d_in[8];
    const float* bout = (const float*)d_in[9];
    float* dout = (float*)d_out;

    int n = in_sizes[0] / HID;
    int E = in_sizes[1] / 2;
    const int* src = ei;
    const int* dst = ei + E;

    int *p_counts, *p_off, *p_cursor, *p_esrc;
    ull *p_x16, *p_h16, *p_aggr16;
    float *p_h2;
    uint4 *p_whi;
    cudaGetSymbolAddress((void**)&p_counts, g_counts);
    cudaGetSymbolAddress((void**)&p_off,    g_off);
    cudaGetSymbolAddress((void**)&p_cursor, g_cursor);
    cudaGetSymbolAddress((void**)&p_esrc,   g_esrc);
    cudaGetSymbolAddress((void**)&p_x16,    g_x16);
    cudaGetSymbolAddress((void**)&p_h16,    g_h16);
    cudaGetSymbolAddress((void**)&p_aggr16, g_aggr16);
    cudaGetSymbolAddress((void**)&p_h2,     g_h2);
    cudaGetSymbolAddress((void**)&p_whi,    g_whi);

    cudaFuncSetAttribute(layer_kernel, cudaFuncAttributeMaxDynamicSharedMemorySize, LAYER_SMEM);

    // tuple output: logits [n*2] then h [n*128]
    float* hOut = ((size_t)out_size >= (size_t)n * (HID + 2)) ? (dout + (size_t)n * 2) : p_h2;

    // ---- launches 1-5: CSR build + W convert + x convert ----
    hist_kernel<<<(E + 255) / 256, 256>>>(dst, p_counts, E);
    scan_kernel<<<1, 1024>>>(p_counts, p_off, p_cursor, n);
    fill_kernel<<<(E + 255) / 256, 256>>>(src, dst, p_cursor, p_esrc, E);
    wsplit_kernel<<<256, 256>>>(W1l, W1r, W2l, W2r);
    int total4 = n * HID / 4;
    xcvt_kernel<<<(total4 + 255) / 256, 256>>>(x, p_x16, total4);

    int gatherGrid = (n * 32 + 255) / 256;
    int nTiles = (n + 127) >> 7;
    int layerGrid = nTiles < 148 ? nTiles : 148;

    // ---- layer 1 (h1 stored fp16) ----
    gather_kernel<<<gatherGrid, 256>>>(p_x16, p_esrc, p_off, p_aggr16, n);
    layer_kernel<<<layerGrid, 256, LAYER_SMEM>>>(p_aggr16, p_x16, p_whi, b1,
                                                 nullptr, p_h16, n, 1);

    // ---- layer 2 (h stored fp32 to output) ----
    gather_kernel<<<gatherGrid, 256>>>(p_h16, p_esrc, p_off, p_aggr16, n);
    layer_kernel<<<layerGrid, 256, LAYER_SMEM>>>(p_aggr16, p_h16, p_whi + 4224, b2,
                                                 hOut, nullptr, n, 0);

    // ---- head ----
    logits_kernel<<<(n * 32 + 255) / 256, 256>>>(hOut, Wout, bout, dout, n);
}

// round 14
// speedup vs baseline: 1.5743x; 1.0167x over previous
#include <cuda_runtime.h>
#include <cuda_bf16.h>
#include <cuda_fp16.h>
#include <cstdint>
#include <math.h>

#define HID 128
#define MAXN 50000
#define MAXE 800000

typedef unsigned long long ull;

// ---------------- scratch (device globals; zero-initialized at load) ----------------
__device__ int   g_counts[MAXN + 1];   // scan_kernel re-zeroes after use each call
__device__ int   g_off[MAXN + 1];
__device__ int   g_cursor[MAXN];
__device__ int   g_esrc[MAXE];
__device__ ull   g_x16[(size_t)MAXN * 32];    // x as fp16 rows (128 halves = 32 ull)
__device__ ull   g_h16[(size_t)MAXN * 32];    // h1 as fp16 rows
__device__ ull   g_aggr16[(size_t)MAXN * 32]; // mean-aggregated features, fp16
__device__ float g_h2[(size_t)MAXN * HID];    // fallback h buffer (fp32)
// W fp16, pre-laid-out as [col][264 halves] (word stride 132), per layer
__device__ uint4 g_whi[2][4224];   // 2 x 67584 B

#define MMA_F16(c, a0, a1, a2, a3, b0, b1) \
    asm volatile("mma.sync.aligned.m16n8k16.row.col.f32.f16.f16.f32 " \
        "{%0,%1,%2,%3}, {%4,%5,%6,%7}, {%8,%9}, {%0,%1,%2,%3};" \
        : "+f"((c)[0]), "+f"((c)[1]), "+f"((c)[2]), "+f"((c)[3]) \
        : "r"(a0), "r"(a1), "r"(a2), "r"(a3), "r"(b0), "r"(b1))

// ---------------- launch 1: edge histogram + x->fp16 convert (fused, independent) ----------------
__global__ void hist_xcvt_kernel(const int* __restrict__ dst, int* __restrict__ counts, int E,
                                 const float* __restrict__ x, ull* __restrict__ x16, int total4) {
    int i = blockIdx.x * blockDim.x + threadIdx.x;
    if (i < E) atomicAdd(&counts[dst[i]], 1);
    if (i < total4) {
        float4 v = ((const float4*)x)[i];
        __half2 h0 = __float22half2_rn(make_float2(v.x, v.y));
        __half2 h1 = __float22half2_rn(make_float2(v.z, v.w));
        x16[i] = (ull)(*(uint32_t*)&h0) | ((ull)(*(uint32_t*)&h1) << 32);
    }
}

// ---------------- launch 2: single-block scan ----------------
__global__ void scan_kernel(int* __restrict__ counts, int* __restrict__ off,
                            int* __restrict__ cursor, int n) {
    __shared__ int part[1024];
    int tid = threadIdx.x;
    int chunk = (n + 1023) >> 10;
    int start = tid * chunk;
    int end = start + chunk; if (end > n) end = n;
    int s = 0;
    #pragma unroll 4
    for (int i = start; i < end; i++) s += counts[i];
    part[tid] = s;
    __syncthreads();
    for (int d = 1; d < 1024; d <<= 1) {
        int v = (tid >= d) ? part[tid - d] : 0;
        __syncthreads();
        part[tid] += v;
        __syncthreads();
    }
    int pre = (tid == 0) ? 0 : part[tid - 1];
    for (int i = start; i < end; i++) {
        int c = counts[i];
        counts[i] = 0;          // leave zeroed for next call's hist
        off[i] = pre;
        cursor[i] = pre;
        pre += c;
    }
    if (end == n) off[n] = pre;
}

// ---------------- launch 3: CSR fill + W fp16 convert (fused, independent) ----------------
__global__ void fill_wsplit_kernel(const int* __restrict__ src, const int* __restrict__ dst,
                                   int* __restrict__ cursor, int* __restrict__ esrc, int E,
                                   const float* __restrict__ W1l, const float* __restrict__ W1r,
                                   const float* __restrict__ W2l, const float* __restrict__ W2r) {
    int i = blockIdx.x * blockDim.x + threadIdx.x;
    if (i < E) {
        int d = dst[i];
        int pos = atomicAdd(&cursor[d], 1);
        esrc[pos] = src[i];
    }
    if (i < 2 * 256 * 128) {
        int layer = i >> 15;
        int r = i & 32767;
        int k = r >> 7;
        int col = r & 127;
        const float* srcm;
        if (layer == 0) srcm = (k < 128) ? (W1l + (size_t)k * 128) : (W1r + (size_t)(k - 128) * 128);
        else            srcm = (k < 128) ? (W2l + (size_t)k * 128) : (W2r + (size_t)(k - 128) * 128);
        float w = srcm[col];
        __half h = __float2half(w);
        ((uint16_t*)g_whi[layer])[col * 264 + k] = *(uint16_t*)&h;
    }
}

// ---------------- gather-aggregate (mean) over fp16 rows: warp per dst node, MLP=8 ----------------
__global__ void gather_kernel(const ull* __restrict__ feat16, const int* __restrict__ esrc,
                              const int* __restrict__ off, ull* __restrict__ aggr16, int n) {
    int w = (blockIdx.x * blockDim.x + threadIdx.x) >> 5;
    int lane = threadIdx.x & 31;
    if (w >= n) return;
    int o0 = off[w], o1 = off[w + 1];
    float a0 = 0.f, a1 = 0.f, a2 = 0.f, a3 = 0.f;
    int k = o0;
    for (; k + 8 <= o1; k += 8) {
        ull vv[8];
        #pragma unroll
        for (int e = 0; e < 8; e++) {
            int s = __ldg(esrc + k + e);
            vv[e] = feat16[(size_t)s * 32 + lane];
        }
        #pragma unroll
        for (int e = 0; e < 8; e++) {
            uint32_t lo = (uint32_t)vv[e], hi = (uint32_t)(vv[e] >> 32);
            float2 f0 = __half22float2(*(__half2*)&lo);
            float2 f1 = __half22float2(*(__half2*)&hi);
            a0 += f0.x; a1 += f0.y; a2 += f1.x; a3 += f1.y;
        }
    }
    for (; k < o1; k++) {
        int s = __ldg(esrc + k);
        ull v = feat16[(size_t)s * 32 + lane];
        uint32_t lo = (uint32_t)v, hi = (uint32_t)(v >> 32);
        float2 f0 = __half22float2(*(__half2*)&lo);
        float2 f1 = __half22float2(*(__half2*)&hi);
        a0 += f0.x; a1 += f0.y; a2 += f1.x; a3 += f1.y;
    }
    float inv = 1.0f / fmaxf((float)(o1 - o0), 1.0f);
    __half2 r0 = __float22half2_rn(make_float2(a0 * inv, a1 * inv));
    __half2 r1 = __float22half2_rn(make_float2(a2 * inv, a3 * inv));
    aggr16[(size_t)w * 32 + lane] = (ull)(*(uint32_t*)&r0) | ((ull)(*(uint32_t*)&r1) << 32);
}

// ---------------- HMMA (mma.sync fp16) SAGE layer, 2 CTAs/SM ----------------
// out[i][j] = relu( b[j] + sum_{k<256} S[i][k] W[k][j] ), S=[A|X] (fp16), W=[Wl;Wr] (fp16).
// Single S buffer, 103KB smem -> 2 resident CTAs per SM interleave stage/MMA phases.
#define WSTRIDE 132
#define SSTRIDE 68
#define SM_BIAS 0
#define SM_WHI  512
#define SM_S    (512 + 128 * WSTRIDE * 4)
#define LAYER_SMEM (SM_S + 128 * SSTRIDE * 4)

__global__ void __launch_bounds__(256, 2)
layer_kernel(const ull* __restrict__ A16, const ull* __restrict__ X16,
             const uint4* __restrict__ whi, const float* __restrict__ bias,
             float* __restrict__ outF32, ull* __restrict__ outF16,
             int n, int outIsF16) {
    extern __shared__ char smem[];
    float* sBias = (float*)(smem + SM_BIAS);
    uint32_t* sWhi = (uint32_t*)(smem + SM_WHI);
    uint32_t* sS   = (uint32_t*)(smem + SM_S);

    int tid = threadIdx.x;
    int wid = tid >> 5;
    int lane = tid & 31;
    int g = lane >> 2;
    int t = lane & 3;
    int n0 = wid * 16;

    // ---- stage W: pure linear copy (4224 uint4) ----
    {
        uint4* dh = (uint4*)sWhi;
        for (int i = tid; i < 4224; i += 256) dh[i] = whi[i];
        if (tid < 128) sBias[tid] = bias[tid];
    }

    int nTiles = (n + 127) >> 7;
    for (int tile = blockIdx.x; tile < nTiles; tile += gridDim.x) {
        float acc[8][2][4];
        #pragma unroll
        for (int m = 0; m < 8; m++)
            #pragma unroll
            for (int nt = 0; nt < 2; nt++)
                #pragma unroll
                for (int q = 0; q < 4; q++) acc[m][nt][q] = 0.f;

        #pragma unroll
        for (int kc = 0; kc < 2; kc++) {
            __syncthreads();   // protects sS reuse (and sW staging on first pass)
            // stage S chunk (128 nodes x 128 k): pure 8B copy, warp = 1 node row / pass
            {
                int q = tid & 31;          // ull index 0..31 within row
                int nl0 = tid >> 5;        // 0..7
                const ull* base = (kc == 0) ? A16 : X16;
                #pragma unroll
                for (int pass = 0; pass < 16; pass++) {
                    int nodeLoc = pass * 8 + nl0;
                    int node = tile * 128 + nodeLoc;
                    ull v = (node < n) ? base[(size_t)node * 32 + q] : 0ull;
                    *(ull*)(sS + nodeLoc * SSTRIDE + 2 * q) = v;
                }
            }
            __syncthreads();

            #pragma unroll
            for (int kstep = 0; kstep < 8; kstep++) {
                int p0 = kstep * 8;
                uint32_t bf[2][2];
                #pragma unroll
                for (int nt = 0; nt < 2; nt++) {
                    int wrow = (n0 + nt * 8 + g) * WSTRIDE + kc * 64 + p0 + t;
                    bf[nt][0] = sWhi[wrow];
                    bf[nt][1] = sWhi[wrow + 4];
                }
                #pragma unroll
                for (int m = 0; m < 8; m++) {
                    int r0 = (m * 16 + g) * SSTRIDE + p0 + t;
                    int r1 = r0 + 8 * SSTRIDE;
                    uint32_t a0 = sS[r0], a1 = sS[r1];
                    uint32_t a2 = sS[r0 + 4], a3 = sS[r1 + 4];
                    #pragma unroll
                    for (int nt = 0; nt < 2; nt++) {
                        MMA_F16(acc[m][nt], a0, a1, a2, a3, bf[nt][0], bf[nt][1]);
                    }
                }
            }
        }

        // epilogue: bias + relu; store fp16 (layer1) or fp32 (layer2).
        #pragma unroll
        for (int m = 0; m < 8; m++) {
            #pragma unroll
            for (int nt = 0; nt < 2; nt++) {
                int col = n0 + nt * 8 + 2 * t;
                float b0 = sBias[col], b1 = sBias[col + 1];
                int node0 = tile * 128 + m * 16 + g;
                int node1 = node0 + 8;
                float v00 = fmaxf(acc[m][nt][0] + b0, 0.f);
                float v01 = fmaxf(acc[m][nt][1] + b1, 0.f);
                float v10 = fmaxf(acc[m][nt][2] + b0, 0.f);
                float v11 = fmaxf(acc[m][nt][3] + b1, 0.f);
                if (outIsF16) {
                    __half* o16 = (__half*)outF16;
                    if (node0 < n) {
                        __half2 h = __float22half2_rn(make_float2(v00, v01));
                        *(__half2*)(o16 + (size_t)node0 * HID + col) = h;
                    }
                    if (node1 < n) {
                        __half2 h = __float22half2_rn(make_float2(v10, v11));
                        *(__half2*)(o16 + (size_t)node1 * HID + col) = h;
                    }
                } else {
                    if (node0 < n) {
                        float2 o; o.x = v00; o.y = v01;
                        *(float2*)(outF32 + (size_t)node0 * HID + col) = o;
                    }
                    if (node1 < n) {
                        float2 o; o.x = v10; o.y = v11;
                        *(float2*)(outF32 + (size_t)node1 * HID + col) = o;
                    }
                }
            }
        }
    }
}

// ---------------- logits head: warp per node ----------------
__global__ void logits_kernel(const float* __restrict__ h, const float* __restrict__ Wout,
                              const float* __restrict__ bout, float* __restrict__ out, int n) {
    int w = (blockIdx.x * blockDim.x + threadIdx.x) >> 5;
    int lane = threadIdx.x & 31;
    if (w >= n) return;
    float4 v = ((const float4*)(h + (size_t)w * HID))[lane];
    int k = lane * 4;
    float s0 = v.x * Wout[(k + 0) * 2 + 0] + v.y * Wout[(k + 1) * 2 + 0] +
               v.z * Wout[(k + 2) * 2 + 0] + v.w * Wout[(k + 3) * 2 + 0];
    float s1 = v.x * Wout[(k + 0) * 2 + 1] + v.y * Wout[(k + 1) * 2 + 1] +
               v.z * Wout[(k + 2) * 2 + 1] + v.w * Wout[(k + 3) * 2 + 1];
    #pragma unroll
    for (int off = 16; off > 0; off >>= 1) {
        s0 += __shfl_xor_sync(0xFFFFFFFFu, s0, off);
        s1 += __shfl_xor_sync(0xFFFFFFFFu, s1, off);
    }
    if (lane == 0) {
        out[(size_t)w * 2 + 0] = s0 + bout[0];
        out[(size_t)w * 2 + 1] = s1 + bout[1];
    }
}

// ---------------- launch ----------------
extern "C" void kernel_launch(void* const* d_in, const int* in_sizes, int n_in,
                              void* d_out, int out_size) {
    const float* x    = (const float*)d_in[0];
    const int*   ei   = (const int*)d_in[1];   // int32 on device
    const float* W1l  = (const float*)d_in[2];
    const float* W1r  = (const float*)d_in[3];
    const float* b1   = (const float*)d_in[4];
    const float* W2l  = (const float*)d_in[5];
    const float* W2r  = (const float*)d_in[6];
    const float* b2   = (const float*)d_in[7];
    const float* Wout = (const float*)d_in[8];
    const float* bout = (const float*)d_in[9];
    float* dout = (float*)d_out;

    int n = in_sizes[0] / HID;
    int E = in_sizes[1] / 2;
    const int* src = ei;
    const int* dst = ei + E;

    int *p_counts, *p_off, *p_cursor, *p_esrc;
    ull *p_x16, *p_h16, *p_aggr16;
    float *p_h2;
    uint4 *p_whi;
    cudaGetSymbolAddress((void**)&p_counts, g_counts);
    cudaGetSymbolAddress((void**)&p_off,    g_off);
    cudaGetSymbolAddress((void**)&p_cursor, g_cursor);
    cudaGetSymbolAddress((void**)&p_esrc,   g_esrc);
    cudaGetSymbolAddress((void**)&p_x16,    g_x16);
    cudaGetSymbolAddress((void**)&p_h16,    g_h16);
    cudaGetSymbolAddress((void**)&p_aggr16, g_aggr16);
    cudaGetSymbolAddress((void**)&p_h2,     g_h2);
    cudaGetSymbolAddress((void**)&p_whi,    g_whi);

    cudaFuncSetAttribute(layer_kernel, cudaFuncAttributeMaxDynamicSharedMemorySize, LAYER_SMEM);

    // tuple output: logits [n*2] then h [n*128]
    float* hOut = ((size_t)out_size >= (size_t)n * (HID + 2)) ? (dout + (size_t)n * 2) : p_h2;

    int total4 = n * HID / 4;
    int grid1 = (max(E, total4) + 255) / 256;

    // ---- launches 1-3 (gather1 is launch #4 -> profiled) ----
    hist_xcvt_kernel<<<grid1, 256>>>(dst, p_counts, E, x, p_x16, total4);
    scan_kernel<<<1, 1024>>>(p_counts, p_off, p_cursor, n);
    fill_wsplit_kernel<<<(E + 255) / 256, 256>>>(src, dst, p_cursor, p_esrc, E,
                                                 W1l, W1r, W2l, W2r);

    int gatherGrid = (n * 32 + 255) / 256;
    int nTiles = (n + 127) >> 7;
    int layerGrid = nTiles < 296 ? nTiles : 296;

    // ---- layer 1 (h1 stored fp16) ----
    gather_kernel<<<gatherGrid, 256>>>(p_x16, p_esrc, p_off, p_aggr16, n);
    layer_kernel<<<layerGrid, 256, LAYER_SMEM>>>(p_aggr16, p_x16, p_whi, b1,
                                                 nullptr, p_h16, n, 1);

    // ---- layer 2 (h stored fp32 to output) ----
    gather_kernel<<<gatherGrid, 256>>>(p_h16, p_esrc, p_off, p_aggr16, n);
    layer_kernel<<<layerGrid, 256, LAYER_SMEM>>>(p_aggr16, p_h16, p_whi + 4224, b2,
                                                 hOut, nullptr, n, 0);

    // ---- head ----
    logits_kernel<<<(n * 32 + 255) / 256, 256>>>(hOut, Wout, bout, dout, n);
}